// round 4
// baseline (speedup 1.0000x reference)
#include <cuda_runtime.h>
#include <cstdint>

#define DIMX 4096      // model dim (= N_HEADS*HEAD_DIM)
#define BQ   8         // batch
#define KVD  1024      // N_KV_HEADS*HEAD_DIM
#define KSPLIT 4

// Scratch (allocation-free rule: __device__ globals)
__device__ float g_xp[KSPLIT][BQ * KVD];  // up-projection partials [4][8,1024]
__device__ float g_y[BQ * DIMX];          // final per-sequence row [8,4096]

__device__ __forceinline__ float warp_sum(float v) {
#pragma unroll
    for (int o = 16; o; o >>= 1) v += __shfl_xor_sync(0xffffffffu, v, o);
    return v;
}

// packed f32x2 FMA (Blackwell): acc(2xf32) += a(2xf32) * b(2xf32)
__device__ __forceinline__ void ffma2(unsigned long long& c,
                                      unsigned long long a,
                                      unsigned long long b) {
    asm("fma.rn.f32x2 %0, %1, %2, %0;" : "+l"(c) : "l"(a), "l"(b));
}

__device__ __forceinline__ float unpack_sum(unsigned long long p) {
    float2 f = *reinterpret_cast<float2*>(&p);
    return f.x + f.y;
}

// ---------------------------------------------------------------------------
// Kernel 1: partial x = E @ W_up^T with 4-way k-split.
// Grid: (256 j-groups, 4 k-slices) x 256 threads. Block: 4 output rows,
// k range [ks*1024, ks*1024+1024). Partials land in g_xp[ks].
// ---------------------------------------------------------------------------
__global__ __launch_bounds__(256) void up_kernel(const float* __restrict__ E,
                                                 const float* __restrict__ Wup) {
    const int tid = threadIdx.x;
    const int j0 = blockIdx.x * 4;
    const int ks = blockIdx.y;
    const int kf = ks * 1024 + tid * 4;  // this thread's 4 k-floats

    float4 e4[8];
#pragma unroll
    for (int b = 0; b < 8; b++)
        e4[b] = *reinterpret_cast<const float4*>(E + b * DIMX + kf);
    float4 w4[4];
#pragma unroll
    for (int r = 0; r < 4; r++)
        w4[r] = *reinterpret_cast<const float4*>(Wup + (size_t)(j0 + r) * DIMX + kf);

    __shared__ float red[8][32];
    const int lane = tid & 31, warp = tid >> 5;
#pragma unroll
    for (int b = 0; b < 8; b++)
#pragma unroll
        for (int r = 0; r < 4; r++) {
            float a = e4[b].x * w4[r].x + e4[b].y * w4[r].y +
                      e4[b].z * w4[r].z + e4[b].w * w4[r].w;
            float s = warp_sum(a);
            if (lane == 0) red[warp][b * 4 + r] = s;
        }
    __syncthreads();
    if (warp == 0) {
        float s = 0.0f;
#pragma unroll
        for (int w = 0; w < 8; w++) s += red[w][lane];
        const int b = lane >> 2, r = lane & 3;
        g_xp[ks][b * KVD + j0 + r] = s;
    }
}

// ---------------------------------------------------------------------------
// Kernel 2: y[8,4096] = expand(x)[8,4096] @ W_down[4096,4096]^T
// Grid: 2048 blocks x 256 threads, 2 output cols per block.
// smem holds un-expanded x [8,1024] (32KB); expansion via folded index
// jsrc = ((j>>9)<<7)|(j&127)  (float4-safe, bank-conflict-free).
// Also sums the k-split partials from kernel 1 during the smem fill.
// ---------------------------------------------------------------------------
__global__ __launch_bounds__(256) void down_kernel(const float* __restrict__ Wdn) {
    __shared__ float s_x[BQ * KVD];  // 32 KB
    const int tid = threadIdx.x;

    // fill: sum 4 partials
    {
        float4* sd = reinterpret_cast<float4*>(s_x);
        const float4* p0 = reinterpret_cast<const float4*>(g_xp[0]);
        const float4* p1 = reinterpret_cast<const float4*>(g_xp[1]);
        const float4* p2 = reinterpret_cast<const float4*>(g_xp[2]);
        const float4* p3 = reinterpret_cast<const float4*>(g_xp[3]);
#pragma unroll
        for (int i = tid; i < BQ * KVD / 4; i += 256) {
            float4 a = p0[i], b = p1[i], c = p2[i], d = p3[i];
            float4 r;
            r.x = (a.x + b.x) + (c.x + d.x);
            r.y = (a.y + b.y) + (c.y + d.y);
            r.z = (a.z + b.z) + (c.z + d.z);
            r.w = (a.w + b.w) + (c.w + d.w);
            sd[i] = r;
        }
    }
    __syncthreads();

    const int i0 = blockIdx.x * 2;

    unsigned long long acc[8][2];
#pragma unroll
    for (int b = 0; b < 8; b++) { acc[b][0] = 0ull; acc[b][1] = 0ull; }

#pragma unroll
    for (int c = 0; c < 4; c++) {
        const int jf = c * 1024 + tid * 4;                    // expanded index
        const int jsrc = ((jf >> 9) << 7) | (jf & 127);       // folded kv index
        ulonglong2 w[2];
#pragma unroll
        for (int r = 0; r < 2; r++)
            w[r] = *reinterpret_cast<const ulonglong2*>(Wdn + (size_t)(i0 + r) * DIMX + jf);
        ulonglong2 v[8];
#pragma unroll
        for (int b = 0; b < 8; b++)
            v[b] = *reinterpret_cast<const ulonglong2*>(s_x + b * KVD + jsrc);
#pragma unroll
        for (int b = 0; b < 8; b++)
#pragma unroll
            for (int r = 0; r < 2; r++) {
                ffma2(acc[b][r], w[r].x, v[b].x);
                ffma2(acc[b][r], w[r].y, v[b].y);
            }
    }

    __shared__ float red[8][16];
    const int lane = tid & 31, warp = tid >> 5;
#pragma unroll
    for (int b = 0; b < 8; b++)
#pragma unroll
        for (int r = 0; r < 2; r++) {
            float s = warp_sum(unpack_sum(acc[b][r]));
            if (lane == 0) red[warp][b * 2 + r] = s;
        }
    __syncthreads();
    if (warp == 0 && lane < 16) {
        float s = 0.0f;
#pragma unroll
        for (int w = 0; w < 8; w++) s += red[w][lane];
        const int b = lane >> 1, r = lane & 1;
        g_y[b * DIMX + i0 + r] = s;
    }
}

// ---------------------------------------------------------------------------
// Kernel 3: broadcast y[b] to all token rows of sequence b (268MB of writes).
// Grid: 2048 blocks x 256 threads, 8 rows per block. Row slice cached in
// registers, reloaded only on sequence change. Streaming stores (__stcs).
// ---------------------------------------------------------------------------
__global__ __launch_bounds__(256) void bcast_kernel(const int* __restrict__ seq,
                                                    float* __restrict__ out,
                                                    int nrows) {
    const int tid = threadIdx.x;

    // seqlen dtype defense: int32 expected; detect int64 (low words) fallback
    int s[8];
#pragma unroll
    for (int i = 0; i < 8; i++) s[i] = __ldg(seq + i);
    int tot = 0;
#pragma unroll
    for (int i = 0; i < 8; i++) tot += s[i];
    if (tot != nrows) {
#pragma unroll
        for (int i = 0; i < 8; i++) s[i] = __ldg(seq + 2 * i);
    }
    int pre[9];
    pre[0] = 0;
#pragma unroll
    for (int i = 0; i < 8; i++) pre[i + 1] = pre[i] + s[i];

    const int r0 = blockIdx.x * 8;
    int r1 = r0 + 8;
    if (r1 > nrows) r1 = nrows;

    int curb = -1;
    float4 v0, v1, v2, v3;

    for (int r = r0; r < r1; ++r) {
        int b = 0;
#pragma unroll
        for (int i = 0; i < 7; i++)
            if (r >= pre[b + 1]) ++b;
        if (b != curb) {
            const float4* yp = reinterpret_cast<const float4*>(g_y + b * DIMX);
            v0 = yp[tid];
            v1 = yp[tid + 256];
            v2 = yp[tid + 512];
            v3 = yp[tid + 768];
            curb = b;
        }
        float4* op = reinterpret_cast<float4*>(out + (size_t)r * DIMX);
        __stcs(op + tid,       v0);
        __stcs(op + tid + 256, v1);
        __stcs(op + tid + 512, v2);
        __stcs(op + tid + 768, v3);
    }
}

// ---------------------------------------------------------------------------
extern "C" void kernel_launch(void* const* d_in, const int* in_sizes, int n_in,
                              void* d_out, int out_size) {
    const float* E   = (const float*)d_in[0];
    const float* Wup = (const float*)d_in[1];
    const float* Wdn = (const float*)d_in[2];
    const int*   seq = (const int*)d_in[3];
    float* out = (float*)d_out;

    const int nrows = out_size / DIMX;  // 16384

    up_kernel<<<dim3(256, KSPLIT), 256>>>(E, Wup);
    down_kernel<<<2048, 256>>>(Wdn);
    bcast_kernel<<<(nrows + 7) / 8, 256>>>(seq, out, nrows);
}

// round 5
// speedup vs baseline: 1.1544x; 1.1544x over previous
#include <cuda_runtime.h>
#include <cstdint>

#define DIMX 4096      // model dim (= N_HEADS*HEAD_DIM)
#define BQ   8         // batch
#define KVD  1024      // N_KV_HEADS*HEAD_DIM

// Scratch (allocation-free rule: __device__ globals)
__device__ float g_x[BQ * KVD];    // up-projection result [8,1024]
__device__ float g_y[BQ * DIMX];   // final per-sequence row [8,4096]

__device__ __forceinline__ float warp_sum(float v) {
#pragma unroll
    for (int o = 16; o; o >>= 1) v += __shfl_xor_sync(0xffffffffu, v, o);
    return v;
}

// packed f32x2 FMA (Blackwell): acc(2xf32) += a(2xf32) * b(2xf32)
__device__ __forceinline__ void ffma2(unsigned long long& c,
                                      unsigned long long a,
                                      unsigned long long b) {
    asm("fma.rn.f32x2 %0, %1, %2, %0;" : "+l"(c) : "l"(a), "l"(b));
}

__device__ __forceinline__ float unpack_sum(unsigned long long p) {
    float2 f = *reinterpret_cast<float2*>(&p);
    return f.x + f.y;
}

// ---------------------------------------------------------------------------
// Kernel 1: x[8,1024] = E[8,4096] @ W_up[1024,1024*4]^T  (GEMV, warp per j)
// Grid: 128 blocks x 256 threads (8 warps). Warp w computes x[:, blk*8+w].
// Each warp streams one 16KB Wup row; E (128KB) hits L1/L2.
// Reduction: 8 warp_sums per warp, amortized over 32-iteration mainloop.
// ---------------------------------------------------------------------------
__global__ __launch_bounds__(256) void up_kernel(const float* __restrict__ E,
                                                 const float* __restrict__ Wup) {
    const int lane = threadIdx.x & 31, warp = threadIdx.x >> 5;
    const int j = blockIdx.x * 8 + warp;

    unsigned long long acc[8];
#pragma unroll
    for (int b = 0; b < 8; b++) acc[b] = 0ull;

    const float* wrow = Wup + (size_t)j * DIMX;

#pragma unroll 4
    for (int it = 0; it < 32; ++it) {
        const int kf = it * 128 + lane * 4;
        const ulonglong2 w4 = *reinterpret_cast<const ulonglong2*>(wrow + kf);
        ulonglong2 e4[8];
#pragma unroll
        for (int b = 0; b < 8; b++)
            e4[b] = *reinterpret_cast<const ulonglong2*>(E + b * DIMX + kf);
#pragma unroll
        for (int b = 0; b < 8; b++) {
            ffma2(acc[b], w4.x, e4[b].x);
            ffma2(acc[b], w4.y, e4[b].y);
        }
    }

#pragma unroll
    for (int b = 0; b < 8; b++) {
        float s = warp_sum(unpack_sum(acc[b]));
        if (lane == 0) g_x[b * KVD + j] = s;
    }
}

// ---------------------------------------------------------------------------
// Kernel 2: y[8,4096] = expand(x)[8,4096] @ W_down[4096,4096]^T (GEMV, warp/i)
// Grid: 512 blocks x 256 threads. Warp w computes y[:, blk*8+w].
// smem holds UN-expanded x [8,1024] (32KB, filled from single g_x — 16MB
// total fill traffic across grid). kv-head expansion via folded index
// jsrc = ((jf>>9)<<7)|(jf&127), float4-aligned, conflict-free.
// ---------------------------------------------------------------------------
__global__ __launch_bounds__(256) void down_kernel(const float* __restrict__ Wdn) {
    __shared__ float s_x[BQ * KVD];  // 32 KB
    const int tid = threadIdx.x;

    {
        float4* sd = reinterpret_cast<float4*>(s_x);
        const float4* sp = reinterpret_cast<const float4*>(g_x);
#pragma unroll
        for (int i = tid; i < BQ * KVD / 4; i += 256) sd[i] = sp[i];
    }
    __syncthreads();

    const int lane = tid & 31, warp = tid >> 5;
    const int i = blockIdx.x * 8 + warp;

    unsigned long long acc[8];
#pragma unroll
    for (int b = 0; b < 8; b++) acc[b] = 0ull;

    const float* wrow = Wdn + (size_t)i * DIMX;

#pragma unroll 4
    for (int it = 0; it < 32; ++it) {
        const int jf = it * 128 + lane * 4;                 // expanded index
        const int jsrc = ((jf >> 9) << 7) | (jf & 127);     // folded kv index
        const ulonglong2 w4 = *reinterpret_cast<const ulonglong2*>(wrow + jf);
        ulonglong2 v[8];
#pragma unroll
        for (int b = 0; b < 8; b++)
            v[b] = *reinterpret_cast<const ulonglong2*>(s_x + b * KVD + jsrc);
#pragma unroll
        for (int b = 0; b < 8; b++) {
            ffma2(acc[b], w4.x, v[b].x);
            ffma2(acc[b], w4.y, v[b].y);
        }
    }

#pragma unroll
    for (int b = 0; b < 8; b++) {
        float s = warp_sum(unpack_sum(acc[b]));
        if (lane == 0) g_y[b * DIMX + i] = s;
    }
}

// ---------------------------------------------------------------------------
// Kernel 3: broadcast y[b] to all token rows of sequence b (268MB of writes).
// Grid: 1024 blocks x 256 threads, 16 rows per block. Row slice cached in
// registers, reloaded only on sequence change. Streaming stores (__stcs).
// ---------------------------------------------------------------------------
__global__ __launch_bounds__(256) void bcast_kernel(const int* __restrict__ seq,
                                                    float* __restrict__ out,
                                                    int nrows) {
    const int tid = threadIdx.x;

    // seqlen dtype defense: int32 expected; detect int64 (low words) fallback
    int s[8];
#pragma unroll
    for (int i = 0; i < 8; i++) s[i] = __ldg(seq + i);
    int tot = 0;
#pragma unroll
    for (int i = 0; i < 8; i++) tot += s[i];
    if (tot != nrows) {
#pragma unroll
        for (int i = 0; i < 8; i++) s[i] = __ldg(seq + 2 * i);
    }
    int pre[9];
    pre[0] = 0;
#pragma unroll
    for (int i = 0; i < 8; i++) pre[i + 1] = pre[i] + s[i];

    const int r0 = blockIdx.x * 16;
    int r1 = r0 + 16;
    if (r1 > nrows) r1 = nrows;

    int curb = -1;
    float4 v0, v1, v2, v3;

    for (int r = r0; r < r1; ++r) {
        int b = 0;
#pragma unroll
        for (int i = 0; i < 7; i++)
            if (r >= pre[b + 1]) ++b;
        if (b != curb) {
            const float4* yp = reinterpret_cast<const float4*>(g_y + b * DIMX);
            v0 = yp[tid];
            v1 = yp[tid + 256];
            v2 = yp[tid + 512];
            v3 = yp[tid + 768];
            curb = b;
        }
        float4* op = reinterpret_cast<float4*>(out + (size_t)r * DIMX);
        __stcs(op + tid,       v0);
        __stcs(op + tid + 256, v1);
        __stcs(op + tid + 512, v2);
        __stcs(op + tid + 768, v3);
    }
}

// ---------------------------------------------------------------------------
extern "C" void kernel_launch(void* const* d_in, const int* in_sizes, int n_in,
                              void* d_out, int out_size) {
    const float* E   = (const float*)d_in[0];
    const float* Wup = (const float*)d_in[1];
    const float* Wdn = (const float*)d_in[2];
    const int*   seq = (const int*)d_in[3];
    float* out = (float*)d_out;

    const int nrows = out_size / DIMX;  // 16384

    up_kernel<<<128, 256>>>(E, Wup);
    down_kernel<<<512, 256>>>(Wdn);
    bcast_kernel<<<(nrows + 15) / 16, 256>>>(seq, out, nrows);
}

// round 6
// speedup vs baseline: 1.6305x; 1.4124x over previous
#include <cuda_runtime.h>
#include <cstdint>

#define DIMX 4096      // model dim (= N_HEADS*HEAD_DIM)
#define BQ   8         // batch
#define KVD  1024      // N_KV_HEADS*HEAD_DIM
#define KS_UP 4        // k-split for up
#define KS_DN 2        // k-split for down

// Scratch (allocation-free rule: __device__ globals)
__device__ float g_xp[KS_UP][BQ * KVD];   // up partials
__device__ float g_x[BQ * KVD];           // summed up result [8,1024]
__device__ float g_yp[KS_DN][BQ * DIMX];  // down partials [2][8,4096]

__device__ __forceinline__ float warp_sum(float v) {
#pragma unroll
    for (int o = 16; o; o >>= 1) v += __shfl_xor_sync(0xffffffffu, v, o);
    return v;
}

// packed f32x2 FMA (Blackwell)
__device__ __forceinline__ void ffma2(unsigned long long& c,
                                      unsigned long long a,
                                      unsigned long long b) {
    asm("fma.rn.f32x2 %0, %1, %2, %0;" : "+l"(c) : "l"(a), "l"(b));
}

__device__ __forceinline__ float unpack_sum(unsigned long long p) {
    float2 f = *reinterpret_cast<float2*>(&p);
    return f.x + f.y;
}

// ---------------------------------------------------------------------------
// Kernel 1: up partials. Grid (128 j-groups, 4 k-slices) x 256.
// Warp w computes j = blkx*8 + w over k in [ks*1024, ks*1024+1024).
// All warps in a block read the SAME E slice -> L1 broadcast.
// ---------------------------------------------------------------------------
__global__ __launch_bounds__(256) void up_kernel(const float* __restrict__ E,
                                                 const float* __restrict__ Wup) {
    const int lane = threadIdx.x & 31, warp = threadIdx.x >> 5;
    const int j  = blockIdx.x * 8 + warp;
    const int ks = blockIdx.y;
    const int k0 = ks * 1024;

    unsigned long long acc[8];
#pragma unroll
    for (int b = 0; b < 8; b++) acc[b] = 0ull;

    const float* wrow = Wup + (size_t)j * DIMX + k0;
    const float* eb   = E + k0;

#pragma unroll 2
    for (int it = 0; it < 8; ++it) {
        const int kf = it * 128 + lane * 4;
        const ulonglong2 w4 = *reinterpret_cast<const ulonglong2*>(wrow + kf);
        ulonglong2 e4[8];
#pragma unroll
        for (int b = 0; b < 8; b++)
            e4[b] = *reinterpret_cast<const ulonglong2*>(eb + b * DIMX + kf);
#pragma unroll
        for (int b = 0; b < 8; b++) {
            ffma2(acc[b], w4.x, e4[b].x);
            ffma2(acc[b], w4.y, e4[b].y);
        }
    }

#pragma unroll
    for (int b = 0; b < 8; b++) {
        float s = warp_sum(unpack_sum(acc[b]));
        if (lane == 0) g_xp[ks][b * KVD + j] = s;
    }
}

// ---------------------------------------------------------------------------
// Kernel 1b: g_x = sum of 4 up partials (8192 floats). 16 blocks x 128.
// ---------------------------------------------------------------------------
__global__ __launch_bounds__(128) void sumx_kernel() {
    const int i = blockIdx.x * 128 + threadIdx.x;  // float4 index, 2048 total
    const float4 a = reinterpret_cast<const float4*>(g_xp[0])[i];
    const float4 b = reinterpret_cast<const float4*>(g_xp[1])[i];
    const float4 c = reinterpret_cast<const float4*>(g_xp[2])[i];
    const float4 d = reinterpret_cast<const float4*>(g_xp[3])[i];
    float4 r;
    r.x = (a.x + b.x) + (c.x + d.x);
    r.y = (a.y + b.y) + (c.y + d.y);
    r.z = (a.z + b.z) + (c.z + d.z);
    r.w = (a.w + b.w) + (c.w + d.w);
    reinterpret_cast<float4*>(g_x)[i] = r;
}

// ---------------------------------------------------------------------------
// Kernel 2: down partials. Grid (512 j-groups, 2 k-halves) x 256.
// Warp w computes y[:, blkx*8+w] over expanded k-half [kh*2048, +2048).
// The kv fold maps this half onto x[:, kh*512 : kh*512+512] -> 16KB smem.
// ---------------------------------------------------------------------------
__global__ __launch_bounds__(256) void down_kernel(const float* __restrict__ Wdn) {
    __shared__ float s_x[BQ * 512];  // 16 KB: x slice for this k-half
    const int tid = threadIdx.x;
    const int kh = blockIdx.y;

    {
        float4* sd = reinterpret_cast<float4*>(s_x);
#pragma unroll
        for (int i = tid; i < BQ * 512 / 4; i += 256) {
            const int b = i >> 7;          // 128 float4 per b
            const int c = i & 127;
            sd[i] = reinterpret_cast<const float4*>(g_x + b * KVD + kh * 512)[c];
        }
    }
    __syncthreads();

    const int lane = tid & 31, warp = tid >> 5;
    const int i = blockIdx.x * 8 + warp;

    unsigned long long acc[8];
#pragma unroll
    for (int b = 0; b < 8; b++) acc[b] = 0ull;

    const float* wrow = Wdn + (size_t)i * DIMX + kh * 2048;

#pragma unroll 2
    for (int it = 0; it < 16; ++it) {
        const int jf = it * 128 + lane * 4;                 // local expanded idx
        const int jsrc = ((jf >> 9) << 7) | (jf & 127);     // folded, in [0,512)
        const ulonglong2 w4 = *reinterpret_cast<const ulonglong2*>(wrow + jf);
        ulonglong2 v[8];
#pragma unroll
        for (int b = 0; b < 8; b++)
            v[b] = *reinterpret_cast<const ulonglong2*>(s_x + b * 512 + jsrc);
#pragma unroll
        for (int b = 0; b < 8; b++) {
            ffma2(acc[b], w4.x, v[b].x);
            ffma2(acc[b], w4.y, v[b].y);
        }
    }

#pragma unroll
    for (int b = 0; b < 8; b++) {
        float s = warp_sum(unpack_sum(acc[b]));
        if (lane == 0) g_yp[kh][b * DIMX + i] = s;
    }
}

// ---------------------------------------------------------------------------
// Kernel 3: broadcast (sums the 2 down partials on each y reload).
// Grid: 1024 blocks x 256, 16 rows/block, streaming stores.
// ---------------------------------------------------------------------------
__global__ __launch_bounds__(256) void bcast_kernel(const int* __restrict__ seq,
                                                    float* __restrict__ out,
                                                    int nrows) {
    const int tid = threadIdx.x;

    // seqlen dtype defense: int32 expected; int64 low-word fallback
    int s[8];
#pragma unroll
    for (int i = 0; i < 8; i++) s[i] = __ldg(seq + i);
    int tot = 0;
#pragma unroll
    for (int i = 0; i < 8; i++) tot += s[i];
    if (tot != nrows) {
#pragma unroll
        for (int i = 0; i < 8; i++) s[i] = __ldg(seq + 2 * i);
    }
    int pre[9];
    pre[0] = 0;
#pragma unroll
    for (int i = 0; i < 8; i++) pre[i + 1] = pre[i] + s[i];

    const int r0 = blockIdx.x * 16;
    int r1 = r0 + 16;
    if (r1 > nrows) r1 = nrows;

    int curb = -1;
    float4 v0, v1, v2, v3;

    for (int r = r0; r < r1; ++r) {
        int b = 0;
#pragma unroll
        for (int i = 0; i < 7; i++)
            if (r >= pre[b + 1]) ++b;
        if (b != curb) {
            const float4* y0 = reinterpret_cast<const float4*>(g_yp[0] + b * DIMX);
            const float4* y1 = reinterpret_cast<const float4*>(g_yp[1] + b * DIMX);
            float4 a, c;
            a = y0[tid];       c = y1[tid];
            v0.x = a.x + c.x; v0.y = a.y + c.y; v0.z = a.z + c.z; v0.w = a.w + c.w;
            a = y0[tid + 256]; c = y1[tid + 256];
            v1.x = a.x + c.x; v1.y = a.y + c.y; v1.z = a.z + c.z; v1.w = a.w + c.w;
            a = y0[tid + 512]; c = y1[tid + 512];
            v2.x = a.x + c.x; v2.y = a.y + c.y; v2.z = a.z + c.z; v2.w = a.w + c.w;
            a = y0[tid + 768]; c = y1[tid + 768];
            v3.x = a.x + c.x; v3.y = a.y + c.y; v3.z = a.z + c.z; v3.w = a.w + c.w;
            curb = b;
        }
        float4* op = reinterpret_cast<float4*>(out + (size_t)r * DIMX);
        __stcs(op + tid,       v0);
        __stcs(op + tid + 256, v1);
        __stcs(op + tid + 512, v2);
        __stcs(op + tid + 768, v3);
    }
}

// ---------------------------------------------------------------------------
extern "C" void kernel_launch(void* const* d_in, const int* in_sizes, int n_in,
                              void* d_out, int out_size) {
    const float* E   = (const float*)d_in[0];
    const float* Wup = (const float*)d_in[1];
    const float* Wdn = (const float*)d_in[2];
    const int*   seq = (const int*)d_in[3];
    float* out = (float*)d_out;

    const int nrows = out_size / DIMX;  // 16384

    up_kernel<<<dim3(128, KS_UP), 256>>>(E, Wup);
    sumx_kernel<<<16, 128>>>();
    down_kernel<<<dim3(512, KS_DN), 256>>>(Wdn);
    bcast_kernel<<<(nrows + 15) / 16, 256>>>(seq, out, nrows);
}